// round 6
// baseline (speedup 1.0000x reference)
#include <cuda_runtime.h>
#include <math.h>

#define B_   256
#define T_   64
#define H_   256
#define D_   512
#define NCTA 128
#define NTHR 256
#define CLSZ 8

#define PAD  260                       // smem row stride (floats), conflict-free
#define SA_OFF   0
#define SWC_OFF  (16 * PAD)            // Wc tile [32][PAD]
#define SWH_OFF  (SWC_OFF + 32 * PAD)  // W_hh gate tiles [3][32][PAD]  (also W2 scratch)
#define SMEM_FLOATS (SWH_OFF + 3 * 32 * PAD)   // 37440 floats = 149760 B

// W2 transpose scratch lives in the sWh region during setup: [512][36]
// STRIDE must be a multiple of 4 so float4 reads at d*STRIDE + 16p + jj are aligned.
#define W2T_STRIDE 36

// ---------------- device scratch (no allocations allowed) -------------------
__device__ __align__(16) float g_u[2][B_ * H_];   // ping-pong state buffers

// ---------------- cluster barrier --------------------------------------------
__device__ __forceinline__ void cbar() {
    __threadfence();   // release: my global stores visible (L2) before peers read
    asm volatile("barrier.cluster.arrive.aligned;" ::: "memory");
    asm volatile("barrier.cluster.wait.aligned;"   ::: "memory");
}

__device__ __forceinline__ float sigm(float x) { return 1.f / (1.f + expf(-x)); }

// ---------------- persistent-group kernel ------------------------------------
__global__ void __launch_bounds__(NTHR, 1) __cluster_dims__(CLSZ, 1, 1)
ode_rnn_kernel(const float* __restrict__ batch, const float* __restrict__ mask,
               const float* __restrict__ W1,   const float* __restrict__ b1,
               const float* __restrict__ W2,   const float* __restrict__ b2,
               const float* __restrict__ W_ih, const float* __restrict__ b_ih,
               const float* __restrict__ W_hh, const float* __restrict__ b_hh,
               float* __restrict__ out)
{
    extern __shared__ float sm[];
    float* sA   = sm + SA_OFF;    // [16][PAD]  A tile (u rows)
    float* sWc  = sm + SWC_OFF;   // [32][PAD]  this CTA's Wc rows n0..n0+31
    float* sWh  = sm + SWH_OFF;   // [3][32][PAD] persistent W_hh gate tiles
    float* sW2T = sm + SWH_OFF;   // setup scratch: W2 tile transposed [512][36]

    const int tid = threadIdx.x;
    const int mt  = blockIdx.x >> 3;       // cluster id = batch-row tile
    const int nt  = blockIdx.x & 7;        // rank in cluster = feature-col tile
    const int m0  = mt << 4;               // 16 batch rows
    const int n0  = nt << 5;               // 32 feature cols
    const int w   = tid >> 5;              // warp 0..7
    const int l   = tid & 31;
    const int jc  = (w << 2) + (l & 3);    // owned col within tile 0..31
    const int r1  = l >> 2;                // owned rows r1, r1+8
    const int r2  = r1 + 8;

    const int b1r = m0 + r1;
    const int b2r = m0 + r2;
    const int j   = n0 + jc;
    const int e1  = b1r * H_ + j;
    const int e2  = b2r * H_ + j;

    // ================= setup (group-local, no grid sync) =================
    // 1) zero this CTA's own chunk of u (group collectively covers its 16 rows)
    g_u[0][e1] = 0.f;
    g_u[0][e2] = 0.f;

    // 2) stage W2 rows n0..n0+31 into smem, transposed: sW2T[d][j']
    for (int idx = tid; idx < 32 * (D_ / 4); idx += NTHR) {
        int jj = idx >> 7;                 // 0..31
        int d4 = (idx & 127) << 2;         // 0,4,...,508
        float4 v = __ldg((const float4*)&W2[(size_t)(n0 + jj) * D_ + d4]);
        sW2T[(d4 + 0) * W2T_STRIDE + jj] = v.x;
        sW2T[(d4 + 1) * W2T_STRIDE + jj] = v.y;
        sW2T[(d4 + 2) * W2T_STRIDE + jj] = v.z;
        sW2T[(d4 + 3) * W2T_STRIDE + jj] = v.w;
    }
    __syncthreads();

    // 3) Wc tile: sWc[j'][h] = sum_d W2[n0+j'][d] * W1[d][h], h = tid
    #pragma unroll
    for (int p = 0; p < 2; p++) {
        float acc[16];
        #pragma unroll
        for (int jj = 0; jj < 16; jj++) acc[jj] = 0.f;
        for (int d = 0; d < D_; d++) {
            float w1v = __ldg(&W1[(size_t)d * H_ + tid]);   // coalesced
            const float* w2d = &sW2T[d * W2T_STRIDE + p * 16];
            #pragma unroll
            for (int jj = 0; jj < 16; jj += 4) {
                float4 wv = *(const float4*)(w2d + jj);     // broadcast, 16B-aligned
                acc[jj + 0] += wv.x * w1v;
                acc[jj + 1] += wv.y * w1v;
                acc[jj + 2] += wv.z * w1v;
                acc[jj + 3] += wv.w * w1v;
            }
        }
        #pragma unroll
        for (int jj = 0; jj < 16; jj++)
            sWc[(p * 16 + jj) * PAD + tid] = acc[jj];
    }
    // bc for this thread's column j (redundant across rows): W2[j,:]·b1 + b2[j]
    float c_bc;
    {
        float s = 0.f;
        for (int d = 0; d < D_; d++)
            s += sW2T[d * W2T_STRIDE + jc] * __ldg(&b1[d]);
        c_bc = s + __ldg(&b2[j]);
    }
    __syncthreads();   // all sW2T reads done before overwrite

    // 4) persistent W_hh gate tiles -> sWh (overwrites scratch)
    for (int idx = tid; idx < 3 * 32 * 64; idx += NTHR) {
        int g = idx >> 11, r = (idx >> 6) & 31, q = (idx & 63) << 2;
        float4 v = __ldg((const float4*)&W_hh[(size_t)(g * H_ + n0 + r) * H_ + q]);
        *(float4*)&sWh[(g * 32 + r) * PAD + q] = v;
    }

    // 5) per-thread constants (column j fixed forever)
    const float c_bhr = __ldg(&b_hh[j]);
    const float c_bhz = __ldg(&b_hh[j + 256]);
    const float c_bhn = __ldg(&b_hh[j + 512]);
    const float c_wir = __ldg(&W_ih[j]);
    const float c_wiz = __ldg(&W_ih[j + 256]);
    const float c_win = __ldg(&W_ih[j + 512]);
    const float c_bir = __ldg(&b_ih[j]);
    const float c_biz = __ldg(&b_ih[j + 256]);
    const float c_bin = __ldg(&b_ih[j + 512]);

    // 6) group-wide: init + smem visible
    __syncthreads();
    cbar();

    const float* pa1 = sA + r1 * PAD;
    const float* pa2 = sA + r2 * PAD;
    const float* pbc = sWc + jc * PAD;
    const float* pbr = sWh + (0 * 32 + jc) * PAD;
    const float* pbz = sWh + (1 * 32 + jc) * PAD;
    const float* pbn = sWh + (2 * 32 + jc) * PAD;

    float ry1 = 0.f, ry2 = 0.f;     // RK4 base state (registers)
    float rk1 = 0.f, rk2 = 0.f;     // RK4 accumulator
    int   pu  = 0;                  // ping-pong parity

    // ================= time loop =================
    float tprev = 0.f;
    for (int t = 0; t < T_; t++) {
        const float tcur  = __ldg(&batch[2 * t]);
        const float hstep = tcur - tprev;      // single RK4 step per interval
        tprev = tcur;

        #pragma unroll
        for (int i = 0; i < 4; i++) {
            // ---- load A tile (u rows m0..m0+15, all 256 cols) from buffer pu ----
            const float* ubuf = g_u[pu];
            #pragma unroll
            for (int rpt = 0; rpt < 4; rpt++) {
                int idx = tid + rpt * NTHR;
                int r = idx >> 6, q = (idx & 63) << 2;
                float4 v = __ldcg((const float4*)&ubuf[(size_t)(m0 + r) * H_ + q]);
                *(float4*)&sA[r * PAD + q] = v;
            }
            __syncthreads();
            // ---- GEMM: 2 dots of K=256 ----
            float acc1 = 0.f, acc2 = 0.f;
            #pragma unroll 16
            for (int k = 0; k < H_; k += 4) {
                float4 b  = *(const float4*)(pbc + k);
                float4 a1 = *(const float4*)(pa1 + k);
                float4 a2 = *(const float4*)(pa2 + k);
                acc1 += a1.x * b.x; acc1 += a1.y * b.y;
                acc1 += a1.z * b.z; acc1 += a1.w * b.w;
                acc2 += a2.x * b.x; acc2 += a2.y * b.y;
                acc2 += a2.z * b.z; acc2 += a2.w * b.w;
            }
            // ---- fused RK4 epilogue ----
            float kv1 = tanhf(acc1 + c_bc);
            float kv2 = tanhf(acc2 + c_bc);
            float u1, u2;
            if (i == 0) {
                rk1 = kv1;              rk2 = kv2;
                u1 = ry1 + 0.5f * hstep * kv1;  u2 = ry2 + 0.5f * hstep * kv2;
            } else if (i == 1) {
                rk1 += 2.f * kv1;       rk2 += 2.f * kv2;
                u1 = ry1 + 0.5f * hstep * kv1;  u2 = ry2 + 0.5f * hstep * kv2;
            } else if (i == 2) {
                rk1 += 2.f * kv1;       rk2 += 2.f * kv2;
                u1 = ry1 + hstep * kv1;         u2 = ry2 + hstep * kv2;
            } else {
                u1 = ry1 + (hstep * (1.f / 6.f)) * (rk1 + kv1);
                u2 = ry2 + (hstep * (1.f / 6.f)) * (rk2 + kv2);
                ry1 = u1; ry2 = u2;
            }
            float* obuf = g_u[pu ^ 1];
            obuf[e1] = u1;
            obuf[e2] = u2;
            pu ^= 1;
            cbar();       // cluster-wide: writes visible, sA reads complete
        }

        // ---- GRU step ----
        {
            const float* ubuf = g_u[pu];
            #pragma unroll
            for (int rpt = 0; rpt < 4; rpt++) {
                int idx = tid + rpt * NTHR;
                int r = idx >> 6, q = (idx & 63) << 2;
                float4 v = __ldcg((const float4*)&ubuf[(size_t)(m0 + r) * H_ + q]);
                *(float4*)&sA[r * PAD + q] = v;
            }
            __syncthreads();
            float ar1 = 0.f, az1 = 0.f, an1 = 0.f;
            float ar2 = 0.f, az2 = 0.f, an2 = 0.f;
            #pragma unroll 8
            for (int k = 0; k < H_; k += 4) {
                float4 a1 = *(const float4*)(pa1 + k);
                float4 a2 = *(const float4*)(pa2 + k);
                float4 br = *(const float4*)(pbr + k);
                float4 bz = *(const float4*)(pbz + k);
                float4 bn = *(const float4*)(pbn + k);
                ar1 += a1.x*br.x + a1.y*br.y + a1.z*br.z + a1.w*br.w;
                az1 += a1.x*bz.x + a1.y*bz.y + a1.z*bz.z + a1.w*bz.w;
                an1 += a1.x*bn.x + a1.y*bn.y + a1.z*bn.z + a1.w*bn.w;
                ar2 += a2.x*br.x + a2.y*br.y + a2.z*br.z + a2.w*br.w;
                az2 += a2.x*bz.x + a2.y*bz.y + a2.z*bz.z + a2.w*bz.w;
                an2 += a2.x*bn.x + a2.y*bn.y + a2.z*bn.z + a2.w*bn.w;
            }
            float* obuf = g_u[pu ^ 1];
            {
                float x1 = __ldg(&batch[(b1r * T_ + t) * 2 + 1]);
                float m1 = __ldg(&mask[b1r * T_ + t]);
                float r_ = sigm(x1 * c_wir + c_bir + ar1 + c_bhr);
                float z_ = sigm(x1 * c_wiz + c_biz + az1 + c_bhz);
                float n_ = tanhf(x1 * c_win + c_bin + r_ * (an1 + c_bhn));
                float ht = (1.f - z_) * n_ + z_ * ry1;
                ry1 = m1 * ht + (1.f - m1) * ry1;
                obuf[e1] = ry1;
                if (t == T_ - 1) out[e1] = ry1;
            }
            {
                float x2 = __ldg(&batch[(b2r * T_ + t) * 2 + 1]);
                float m2 = __ldg(&mask[b2r * T_ + t]);
                float r_ = sigm(x2 * c_wir + c_bir + ar2 + c_bhr);
                float z_ = sigm(x2 * c_wiz + c_biz + az2 + c_bhz);
                float n_ = tanhf(x2 * c_win + c_bin + r_ * (an2 + c_bhn));
                float ht = (1.f - z_) * n_ + z_ * ry2;
                ry2 = m2 * ht + (1.f - m2) * ry2;
                obuf[e2] = ry2;
                if (t == T_ - 1) out[e2] = ry2;
            }
            pu ^= 1;
            cbar();
        }
    }
}

extern "C" void kernel_launch(void* const* d_in, const int* in_sizes, int n_in,
                              void* d_out, int out_size) {
    const float* batch = (const float*)d_in[0];
    const float* mask  = (const float*)d_in[1];
    const float* W1    = (const float*)d_in[2];
    const float* b1    = (const float*)d_in[3];
    const float* W2    = (const float*)d_in[4];
    const float* b2    = (const float*)d_in[5];
    const float* W_ih  = (const float*)d_in[6];
    const float* b_ih  = (const float*)d_in[7];
    const float* W_hh  = (const float*)d_in[8];
    const float* b_hh  = (const float*)d_in[9];
    float* out = (float*)d_out;

    cudaFuncSetAttribute(ode_rnn_kernel,
                         cudaFuncAttributeMaxDynamicSharedMemorySize,
                         SMEM_FLOATS * sizeof(float));

    ode_rnn_kernel<<<NCTA, NTHR, SMEM_FLOATS * sizeof(float)>>>(
        batch, mask, W1, b1, W2, b2, W_ih, b_ih, W_hh, b_hh, out);
}

// round 7
// speedup vs baseline: 1.1702x; 1.1702x over previous
#include <cuda_runtime.h>
#include <math.h>

#define B_   256
#define T_   64
#define H_   256
#define D_   512
#define NCTA 128
#define NTHR 256
#define CLSZ 8

#define PAD  260                        // smem row stride (floats), conflict-free
#define SA0_OFF  0                      // A tile buffer 0  [16][PAD]
#define SA1_OFF  (16 * PAD)             // A tile buffer 1  [16][PAD]
#define SWC_OFF  (32 * PAD)             // Wc tile [32][PAD]
#define SWH_OFF  (64 * PAD)             // W_hh gate tiles [3][32][PAD] (+setup scratch)
#define SMEM_FLOATS (SWH_OFF + 3 * 32 * PAD)   // 160*260 = 41600 fl = 166400 B

#define W2T_STRIDE 36                   // multiple of 4: float4-aligned scratch rows
#define TX_BYTES (16 * H_ * 4)          // inbound bytes per stage = 16384

__device__ __forceinline__ unsigned s2u(const void* p) {
    unsigned a;
    asm("{ .reg .u64 t; cvta.to.shared.u64 t, %1; cvt.u32.u64 %0, t; }"
        : "=r"(a) : "l"(p));
    return a;
}

__device__ __forceinline__ void mwait(unsigned mbar, unsigned parity) {
    asm volatile(
        "{\n\t"
        ".reg .pred P;\n\t"
        "MW_LOOP_%=:\n\t"
        "mbarrier.try_wait.parity.shared.b64 P, [%0], %1;\n\t"
        "@!P bra MW_LOOP_%=;\n\t"
        "}"
        :: "r"(mbar), "r"(parity) : "memory");
}

__device__ __forceinline__ void expect_tx(unsigned mbar, unsigned bytes) {
    asm volatile("mbarrier.arrive.expect_tx.shared.b64 _, [%0], %1;"
                 :: "r"(mbar), "r"(bytes) : "memory");
}

__device__ __forceinline__ void st_async(unsigned daddr, float v, unsigned mbar) {
    asm volatile("st.async.shared::cluster.mbarrier::complete_tx::bytes.f32 [%0], %1, [%2];"
                 :: "r"(daddr), "f"(v), "r"(mbar) : "memory");
}

__device__ __forceinline__ float sigm(float x) { return 1.f / (1.f + expf(-x)); }

// ---------------- persistent-group kernel ------------------------------------
__global__ void __launch_bounds__(NTHR, 1) __cluster_dims__(CLSZ, 1, 1)
ode_rnn_kernel(const float* __restrict__ batch, const float* __restrict__ mask,
               const float* __restrict__ W1,   const float* __restrict__ b1,
               const float* __restrict__ W2,   const float* __restrict__ b2,
               const float* __restrict__ W_ih, const float* __restrict__ b_ih,
               const float* __restrict__ W_hh, const float* __restrict__ b_hh,
               float* __restrict__ out)
{
    extern __shared__ float sm[];
    float* sWc  = sm + SWC_OFF;   // [32][PAD]  this CTA's Wc rows n0..n0+31
    float* sWh  = sm + SWH_OFF;   // [3][32][PAD] persistent W_hh gate tiles
    float* sW2T = sm + SWH_OFF;   // setup scratch: W2 tile transposed [512][36]

    __shared__ __align__(16) unsigned long long s_mbar[2];

    const int tid = threadIdx.x;
    const int mt  = blockIdx.x >> 3;       // cluster id = batch-row tile
    const int nt  = blockIdx.x & 7;        // rank in cluster = feature-col tile
    const int m0  = mt << 4;               // 16 batch rows
    const int n0  = nt << 5;               // 32 feature cols
    const int w   = tid >> 5;              // warp 0..7
    const int l   = tid & 31;
    const int jc  = (w << 2) + (l & 3);    // owned col within tile 0..31
    const int r1  = l >> 2;                // owned rows r1, r1+8
    const int r2  = r1 + 8;

    const int b1r = m0 + r1;
    const int b2r = m0 + r2;
    const int j   = n0 + jc;

    const unsigned smbase = s2u(sm);
    const unsigned mbase  = s2u(s_mbar);

    // ================= setup (group-local) =================
    // zero A buffer 0 (u0 = 0), each CTA its own copy
    for (int idx = tid; idx < 16 * PAD; idx += NTHR) sm[SA0_OFF + idx] = 0.f;

    // stage W2 rows n0..n0+31 into smem, transposed: sW2T[d][j']
    for (int idx = tid; idx < 32 * (D_ / 4); idx += NTHR) {
        int jj = idx >> 7;                 // 0..31
        int d4 = (idx & 127) << 2;         // 0,4,...,508
        float4 v = __ldg((const float4*)&W2[(size_t)(n0 + jj) * D_ + d4]);
        sW2T[(d4 + 0) * W2T_STRIDE + jj] = v.x;
        sW2T[(d4 + 1) * W2T_STRIDE + jj] = v.y;
        sW2T[(d4 + 2) * W2T_STRIDE + jj] = v.z;
        sW2T[(d4 + 3) * W2T_STRIDE + jj] = v.w;
    }
    __syncthreads();

    // Wc tile: sWc[j'][h] = sum_d W2[n0+j'][d] * W1[d][h], h = tid
    #pragma unroll
    for (int p = 0; p < 2; p++) {
        float acc[16];
        #pragma unroll
        for (int jj = 0; jj < 16; jj++) acc[jj] = 0.f;
        for (int d = 0; d < D_; d++) {
            float w1v = __ldg(&W1[(size_t)d * H_ + tid]);   // coalesced
            const float* w2d = &sW2T[d * W2T_STRIDE + p * 16];
            #pragma unroll
            for (int jj = 0; jj < 16; jj += 4) {
                float4 wv = *(const float4*)(w2d + jj);     // aligned broadcast
                acc[jj + 0] += wv.x * w1v;
                acc[jj + 1] += wv.y * w1v;
                acc[jj + 2] += wv.z * w1v;
                acc[jj + 3] += wv.w * w1v;
            }
        }
        #pragma unroll
        for (int jj = 0; jj < 16; jj++)
            sWc[(p * 16 + jj) * PAD + tid] = acc[jj];
    }
    // bc for this thread's fixed column j
    float c_bc;
    {
        float s = 0.f;
        for (int d = 0; d < D_; d++)
            s += sW2T[d * W2T_STRIDE + jc] * __ldg(&b1[d]);
        c_bc = s + __ldg(&b2[j]);
    }
    __syncthreads();   // sW2T reads done before overwrite

    // persistent W_hh gate tiles (overwrites scratch)
    for (int idx = tid; idx < 3 * 32 * 64; idx += NTHR) {
        int g = idx >> 11, r = (idx >> 6) & 31, q = (idx & 63) << 2;
        float4 v = __ldg((const float4*)&W_hh[(size_t)(g * H_ + n0 + r) * H_ + q]);
        *(float4*)&sWh[(g * 32 + r) * PAD + q] = v;
    }

    // per-thread constants
    const float c_bhr = __ldg(&b_hh[j]);
    const float c_bhz = __ldg(&b_hh[j + 256]);
    const float c_bhn = __ldg(&b_hh[j + 512]);
    const float c_wir = __ldg(&W_ih[j]);
    const float c_wiz = __ldg(&W_ih[j + 256]);
    const float c_win = __ldg(&W_ih[j + 512]);
    const float c_bir = __ldg(&b_ih[j]);
    const float c_biz = __ldg(&b_ih[j + 256]);
    const float c_bin = __ldg(&b_ih[j + 512]);

    // mbarriers: 1 expected arrival per phase (the local expect_tx)
    if (tid == 0) {
        asm volatile("mbarrier.init.shared.b64 [%0], 1;" :: "r"(mbase)     : "memory");
        asm volatile("mbarrier.init.shared.b64 [%0], 1;" :: "r"(mbase + 8) : "memory");
    }
    __syncthreads();
    // one-time cluster sync: mbarriers + smem init visible before any st.async
    asm volatile("barrier.cluster.arrive.aligned;" ::: "memory");
    asm volatile("barrier.cluster.wait.aligned;"   ::: "memory");

    // remote bases for all 8 cluster ranks
    unsigned rbase[CLSZ], rmbar[CLSZ];
    #pragma unroll
    for (int p = 0; p < CLSZ; p++) {
        asm("mapa.shared::cluster.u32 %0, %1, %2;" : "=r"(rbase[p]) : "r"(smbase), "r"(p));
        asm("mapa.shared::cluster.u32 %0, %1, %2;" : "=r"(rmbar[p]) : "r"(mbase),  "r"(p));
    }

    const unsigned jOff1 = (unsigned)(r1 * PAD + j) * 4u;         // within-buffer byte offsets
    const unsigned jOff2 = jOff1 + 8u * PAD * 4u;

    float ry1 = 0.f, ry2 = 0.f;     // RK4 base state (registers)
    float rk1 = 0.f, rk2 = 0.f;     // RK4 accumulator

    // ================= time loop =================
    int   s = 0;                    // global stage/phase index (5 per timestep)
    float tprev = 0.f;
    for (int t = 0; t < T_; t++) {
        const float tcur  = __ldg(&batch[2 * t]);
        const float hstep = tcur - tprev;      // single RK4 step per interval
        tprev = tcur;

        #pragma unroll
        for (int i = 0; i < 4; i++) {
            // ---- stage prologue ----
            const unsigned mb_cur = mbase + (unsigned)((s & 1) << 3);
            if (tid == 0) expect_tx(mb_cur, TX_BYTES);
            if (s > 0) mwait(mbase + (unsigned)(((s - 1) & 1) << 3),
                             (unsigned)(((s - 1) >> 1) & 1));
            const float* Ab = sm + ((s & 1) ? SA1_OFF : SA0_OFF);
            const float* pa1 = Ab + r1 * PAD;
            const float* pa2 = Ab + r2 * PAD;
            const float* pbc = sWc + jc * PAD;
            // ---- GEMM: 2 dots of K=256 ----
            float acc1 = 0.f, acc2 = 0.f;
            #pragma unroll 16
            for (int k = 0; k < H_; k += 4) {
                float4 b  = *(const float4*)(pbc + k);
                float4 a1 = *(const float4*)(pa1 + k);
                float4 a2 = *(const float4*)(pa2 + k);
                acc1 += a1.x * b.x; acc1 += a1.y * b.y;
                acc1 += a1.z * b.z; acc1 += a1.w * b.w;
                acc2 += a2.x * b.x; acc2 += a2.y * b.y;
                acc2 += a2.z * b.z; acc2 += a2.w * b.w;
            }
            // ---- fused RK4 epilogue ----
            float kv1 = tanhf(acc1 + c_bc);
            float kv2 = tanhf(acc2 + c_bc);
            float u1, u2;
            if (i == 0) {
                rk1 = kv1;              rk2 = kv2;
                u1 = ry1 + 0.5f * hstep * kv1;  u2 = ry2 + 0.5f * hstep * kv2;
            } else if (i == 1) {
                rk1 += 2.f * kv1;       rk2 += 2.f * kv2;
                u1 = ry1 + 0.5f * hstep * kv1;  u2 = ry2 + 0.5f * hstep * kv2;
            } else if (i == 2) {
                rk1 += 2.f * kv1;       rk2 += 2.f * kv2;
                u1 = ry1 + hstep * kv1;         u2 = ry2 + hstep * kv2;
            } else {
                u1 = ry1 + (hstep * (1.f / 6.f)) * (rk1 + kv1);
                u2 = ry2 + (hstep * (1.f / 6.f)) * (rk2 + kv2);
                ry1 = u1; ry2 = u2;
            }
            // ---- push into every CTA's next A buffer ----
            const unsigned dstOff = ((s & 1) ? SA0_OFF : SA1_OFF) * 4u;
            const unsigned o1 = dstOff + jOff1;
            const unsigned o2 = dstOff + jOff2;
            #pragma unroll
            for (int p = 0; p < CLSZ; p++) {
                const unsigned mb = rmbar[p] + (unsigned)((s & 1) << 3);
                st_async(rbase[p] + o1, u1, mb);
                st_async(rbase[p] + o2, u2, mb);
            }
            s++;
        }

        // ---- GRU stage ----
        {
            const bool last = (t == T_ - 1);
            const unsigned mb_cur = mbase + (unsigned)((s & 1) << 3);
            if (tid == 0 && !last) expect_tx(mb_cur, TX_BYTES);
            mwait(mbase + (unsigned)(((s - 1) & 1) << 3),
                  (unsigned)(((s - 1) >> 1) & 1));
            const float* Ab = sm + ((s & 1) ? SA1_OFF : SA0_OFF);
            const float* pa1 = Ab + r1 * PAD;
            const float* pa2 = Ab + r2 * PAD;
            const float* pbr = sWh + (0 * 32 + jc) * PAD;
            const float* pbz = sWh + (1 * 32 + jc) * PAD;
            const float* pbn = sWh + (2 * 32 + jc) * PAD;

            float ar1 = 0.f, az1 = 0.f, an1 = 0.f;
            float ar2 = 0.f, az2 = 0.f, an2 = 0.f;
            #pragma unroll 8
            for (int k = 0; k < H_; k += 4) {
                float4 a1 = *(const float4*)(pa1 + k);
                float4 a2 = *(const float4*)(pa2 + k);
                float4 br = *(const float4*)(pbr + k);
                float4 bz = *(const float4*)(pbz + k);
                float4 bn = *(const float4*)(pbn + k);
                ar1 += a1.x*br.x + a1.y*br.y + a1.z*br.z + a1.w*br.w;
                az1 += a1.x*bz.x + a1.y*bz.y + a1.z*bz.z + a1.w*bz.w;
                an1 += a1.x*bn.x + a1.y*bn.y + a1.z*bn.z + a1.w*bn.w;
                ar2 += a2.x*br.x + a2.y*br.y + a2.z*br.z + a2.w*br.w;
                az2 += a2.x*bz.x + a2.y*bz.y + a2.z*bz.z + a2.w*bz.w;
                an2 += a2.x*bn.x + a2.y*bn.y + a2.z*bn.z + a2.w*bn.w;
            }
            {
                float x1 = __ldg(&batch[(b1r * T_ + t) * 2 + 1]);
                float m1 = __ldg(&mask[b1r * T_ + t]);
                float r_ = sigm(x1 * c_wir + c_bir + ar1 + c_bhr);
                float z_ = sigm(x1 * c_wiz + c_biz + az1 + c_bhz);
                float n_ = tanhf(x1 * c_win + c_bin + r_ * (an1 + c_bhn));
                float ht = (1.f - z_) * n_ + z_ * ry1;
                ry1 = m1 * ht + (1.f - m1) * ry1;
            }
            {
                float x2 = __ldg(&batch[(b2r * T_ + t) * 2 + 1]);
                float m2 = __ldg(&mask[b2r * T_ + t]);
                float r_ = sigm(x2 * c_wir + c_bir + ar2 + c_bhr);
                float z_ = sigm(x2 * c_wiz + c_biz + az2 + c_bhz);
                float n_ = tanhf(x2 * c_win + c_bin + r_ * (an2 + c_bhn));
                float ht = (1.f - z_) * n_ + z_ * ry2;
                ry2 = m2 * ht + (1.f - m2) * ry2;
            }
            if (!last) {
                const unsigned dstOff = ((s & 1) ? SA0_OFF : SA1_OFF) * 4u;
                const unsigned o1 = dstOff + jOff1;
                const unsigned o2 = dstOff + jOff2;
                #pragma unroll
                for (int p = 0; p < CLSZ; p++) {
                    const unsigned mb = rmbar[p] + (unsigned)((s & 1) << 3);
                    st_async(rbase[p] + o1, ry1, mb);
                    st_async(rbase[p] + o2, ry2, mb);
                }
            } else {
                out[b1r * H_ + j] = ry1;
                out[b2r * H_ + j] = ry2;
            }
            s++;
        }
    }
}

extern "C" void kernel_launch(void* const* d_in, const int* in_sizes, int n_in,
                              void* d_out, int out_size) {
    const float* batch = (const float*)d_in[0];
    const float* mask  = (const float*)d_in[1];
    const float* W1    = (const float*)d_in[2];
    const float* b1    = (const float*)d_in[3];
    const float* W2    = (const float*)d_in[4];
    const float* b2    = (const float*)d_in[5];
    const float* W_ih  = (const float*)d_in[6];
    const float* b_ih  = (const float*)d_in[7];
    const float* W_hh  = (const float*)d_in[8];
    const float* b_hh  = (const float*)d_in[9];
    float* out = (float*)d_out;

    cudaFuncSetAttribute(ode_rnn_kernel,
                         cudaFuncAttributeMaxDynamicSharedMemorySize,
                         SMEM_FLOATS * sizeof(float));

    ode_rnn_kernel<<<NCTA, NTHR, SMEM_FLOATS * sizeof(float)>>>(
        batch, mask, W1, b1, W2, b2, W_ih, b_ih, W_hh, b_hh, out);
}

// round 8
// speedup vs baseline: 1.5107x; 1.2910x over previous
#include <cuda_runtime.h>
#include <math.h>

#define B_   256
#define T_   64
#define H_   256
#define D_   512
#define NCTA 128
#define NTHR 256
#define CLSZ 8

#define PAD  260                        // smem row stride (floats), conflict-free
#define SA0_OFF  0                      // A tile buffer 0  [16][PAD]
#define SA1_OFF  (16 * PAD)             // A tile buffer 1  [16][PAD]
#define SWC_OFF  (32 * PAD)             // Wc tile [32][PAD]
#define SWH_OFF  (64 * PAD)             // W_hh gate tiles [3][32][PAD] (+setup scratch)
#define SMEM_FLOATS (SWH_OFF + 3 * 32 * PAD)   // 160*260 = 41600 fl = 166400 B

#define W2T_STRIDE 36                   // multiple of 4: float4-aligned scratch rows
#define TX_BYTES (16 * H_ * 4)          // inbound bytes per stage = 16384

__device__ __forceinline__ unsigned s2u(const void* p) {
    unsigned a;
    asm("{ .reg .u64 t; cvta.to.shared.u64 t, %1; cvt.u32.u64 %0, t; }"
        : "=r"(a) : "l"(p));
    return a;
}

__device__ __forceinline__ void mwait(unsigned mbar, unsigned parity) {
    asm volatile(
        "{\n\t"
        ".reg .pred P;\n\t"
        "MW_LOOP_%=:\n\t"
        "mbarrier.try_wait.parity.shared.b64 P, [%0], %1;\n\t"
        "@!P bra MW_LOOP_%=;\n\t"
        "}"
        :: "r"(mbar), "r"(parity) : "memory");
}

__device__ __forceinline__ void expect_tx(unsigned mbar, unsigned bytes) {
    asm volatile("mbarrier.arrive.expect_tx.shared.b64 _, [%0], %1;"
                 :: "r"(mbar), "r"(bytes) : "memory");
}

__device__ __forceinline__ void st_async(unsigned daddr, float v, unsigned mbar) {
    asm volatile("st.async.shared::cluster.mbarrier::complete_tx::bytes.f32 [%0], %1, [%2];"
                 :: "r"(daddr), "f"(v), "r"(mbar) : "memory");
}

__device__ __forceinline__ float sigm(float x) { return 1.f / (1.f + expf(-x)); }

// ---------------- persistent-group kernel ------------------------------------
__global__ void __launch_bounds__(NTHR, 1) __cluster_dims__(CLSZ, 1, 1)
ode_rnn_kernel(const float* __restrict__ batch, const float* __restrict__ mask,
               const float* __restrict__ W1,   const float* __restrict__ b1,
               const float* __restrict__ W2,   const float* __restrict__ b2,
               const float* __restrict__ W_ih, const float* __restrict__ b_ih,
               const float* __restrict__ W_hh, const float* __restrict__ b_hh,
               float* __restrict__ out)
{
    extern __shared__ float sm[];
    float* sWc  = sm + SWC_OFF;   // [32][PAD]  this CTA's Wc rows n0..n0+31
    float* sWh  = sm + SWH_OFF;   // [3][32][PAD] persistent W_hh gate tiles
    float* sW2T = sm + SWH_OFF;   // setup scratch: W2 tile transposed [512][36]

    __shared__ __align__(16) unsigned long long s_mbar[2];

    const int tid = threadIdx.x;
    const int mt  = blockIdx.x >> 3;       // cluster id = batch-row tile
    const int nt  = blockIdx.x & 7;        // rank in cluster = feature-col tile
    const int m0  = mt << 4;               // 16 batch rows
    const int n0  = nt << 5;               // 32 feature cols
    const int w   = tid >> 5;              // warp 0..7
    const int l   = tid & 31;
    // NEW mapping: lane = column (unique b), warp = row pair (broadcast a)
    const int jc  = l;                     // owned col within tile 0..31
    const int r1  = w;                     // owned rows w, w+8
    const int r2  = w + 8;

    const int b1r = m0 + r1;
    const int b2r = m0 + r2;
    const int j   = n0 + jc;

    const unsigned smbase = s2u(sm);
    const unsigned mbase  = s2u(s_mbar);

    // ================= setup (group-local) =================
    // zero A buffer 0 (u0 = 0), each CTA its own copy
    for (int idx = tid; idx < 16 * PAD; idx += NTHR) sm[SA0_OFF + idx] = 0.f;

    // stage W2 rows n0..n0+31 into smem, transposed: sW2T[d][j']
    for (int idx = tid; idx < 32 * (D_ / 4); idx += NTHR) {
        int jj = idx >> 7;                 // 0..31
        int d4 = (idx & 127) << 2;         // 0,4,...,508
        float4 v = __ldg((const float4*)&W2[(size_t)(n0 + jj) * D_ + d4]);
        sW2T[(d4 + 0) * W2T_STRIDE + jj] = v.x;
        sW2T[(d4 + 1) * W2T_STRIDE + jj] = v.y;
        sW2T[(d4 + 2) * W2T_STRIDE + jj] = v.z;
        sW2T[(d4 + 3) * W2T_STRIDE + jj] = v.w;
    }
    __syncthreads();

    // Wc tile: sWc[j'][h] = sum_d W2[n0+j'][d] * W1[d][h], h = tid
    #pragma unroll
    for (int p = 0; p < 2; p++) {
        float acc[16];
        #pragma unroll
        for (int jj = 0; jj < 16; jj++) acc[jj] = 0.f;
        for (int d = 0; d < D_; d++) {
            float w1v = __ldg(&W1[(size_t)d * H_ + tid]);   // coalesced
            const float* w2d = &sW2T[d * W2T_STRIDE + p * 16];
            #pragma unroll
            for (int jj = 0; jj < 16; jj += 4) {
                float4 wv = *(const float4*)(w2d + jj);     // aligned broadcast
                acc[jj + 0] += wv.x * w1v;
                acc[jj + 1] += wv.y * w1v;
                acc[jj + 2] += wv.z * w1v;
                acc[jj + 3] += wv.w * w1v;
            }
        }
        #pragma unroll
        for (int jj = 0; jj < 16; jj++)
            sWc[(p * 16 + jj) * PAD + tid] = acc[jj];
    }
    // bc for this thread's fixed column j
    float c_bc;
    {
        float s = 0.f;
        for (int d = 0; d < D_; d++)
            s += sW2T[d * W2T_STRIDE + jc] * __ldg(&b1[d]);
        c_bc = s + __ldg(&b2[j]);
    }
    __syncthreads();   // sW2T reads done before overwrite

    // persistent W_hh gate tiles (overwrites scratch)
    for (int idx = tid; idx < 3 * 32 * 64; idx += NTHR) {
        int g = idx >> 11, r = (idx >> 6) & 31, q = (idx & 63) << 2;
        float4 v = __ldg((const float4*)&W_hh[(size_t)(g * H_ + n0 + r) * H_ + q]);
        *(float4*)&sWh[(g * 32 + r) * PAD + q] = v;
    }

    // per-thread constants
    const float c_bhr = __ldg(&b_hh[j]);
    const float c_bhz = __ldg(&b_hh[j + 256]);
    const float c_bhn = __ldg(&b_hh[j + 512]);
    const float c_wir = __ldg(&W_ih[j]);
    const float c_wiz = __ldg(&W_ih[j + 256]);
    const float c_win = __ldg(&W_ih[j + 512]);
    const float c_bir = __ldg(&b_ih[j]);
    const float c_biz = __ldg(&b_ih[j + 256]);
    const float c_bin = __ldg(&b_ih[j + 512]);

    // mbarriers: 1 expected arrival per phase (the local expect_tx)
    if (tid == 0) {
        asm volatile("mbarrier.init.shared.b64 [%0], 1;" :: "r"(mbase)     : "memory");
        asm volatile("mbarrier.init.shared.b64 [%0], 1;" :: "r"(mbase + 8) : "memory");
    }
    __syncthreads();
    // one-time cluster sync: mbarriers + smem init visible before any st.async
    asm volatile("barrier.cluster.arrive.aligned;" ::: "memory");
    asm volatile("barrier.cluster.wait.aligned;"   ::: "memory");

    // remote bases for all 8 cluster ranks
    unsigned rbase[CLSZ], rmbar[CLSZ];
    #pragma unroll
    for (int p = 0; p < CLSZ; p++) {
        asm("mapa.shared::cluster.u32 %0, %1, %2;" : "=r"(rbase[p]) : "r"(smbase), "r"(p));
        asm("mapa.shared::cluster.u32 %0, %1, %2;" : "=r"(rmbar[p]) : "r"(mbase),  "r"(p));
    }

    const unsigned jOff1 = (unsigned)(r1 * PAD + j) * 4u;   // within-buffer byte offsets
    const unsigned jOff2 = (unsigned)(r2 * PAD + j) * 4u;

    const float* pbc = sWc + jc * PAD;                 // unique per lane
    const float* pbr = sWh + (0 * 32 + jc) * PAD;
    const float* pbz = sWh + (1 * 32 + jc) * PAD;
    const float* pbn = sWh + (2 * 32 + jc) * PAD;

    float ry1 = 0.f, ry2 = 0.f;     // ODE base state (registers)
    float k11 = 0.f, k12 = 0.f;     // RK3 k1 keep

    // ================= time loop =================
    int   s = 0;                    // global stage index (4 per timestep)
    float tprev = 0.f;
    for (int t = 0; t < T_; t++) {
        const float tcur  = __ldg(&batch[2 * t]);
        const float hstep = tcur - tprev;      // single RK3 step per interval
        tprev = tcur;

        #pragma unroll
        for (int i = 0; i < 3; i++) {
            // ---- stage prologue ----
            const unsigned mb_cur = mbase + (unsigned)((s & 1) << 3);
            if (tid == 0) expect_tx(mb_cur, TX_BYTES);
            if (s > 0) mwait(mbase + (unsigned)(((s - 1) & 1) << 3),
                             (unsigned)(((s - 1) >> 1) & 1));
            const float* Ab = sm + ((s & 1) ? SA1_OFF : SA0_OFF);
            const float* pa1 = Ab + r1 * PAD;   // warp-broadcast addresses
            const float* pa2 = Ab + r2 * PAD;
            // ---- GEMM: 2 dots of K=256 (2 partial chains each) ----
            float a1a = 0.f, a1b = 0.f, a2a = 0.f, a2b = 0.f;
            #pragma unroll 8
            for (int k = 0; k < H_; k += 8) {
                float4 bx = *(const float4*)(pbc + k);
                float4 u1 = *(const float4*)(pa1 + k);
                float4 u2 = *(const float4*)(pa2 + k);
                a1a += u1.x * bx.x; a1a += u1.y * bx.y;
                a1a += u1.z * bx.z; a1a += u1.w * bx.w;
                a2a += u2.x * bx.x; a2a += u2.y * bx.y;
                a2a += u2.z * bx.z; a2a += u2.w * bx.w;
                float4 by = *(const float4*)(pbc + k + 4);
                float4 v1 = *(const float4*)(pa1 + k + 4);
                float4 v2 = *(const float4*)(pa2 + k + 4);
                a1b += v1.x * by.x; a1b += v1.y * by.y;
                a1b += v1.z * by.z; a1b += v1.w * by.w;
                a2b += v2.x * by.x; a2b += v2.y * by.y;
                a2b += v2.z * by.z; a2b += v2.w * by.w;
            }
            float kv1 = tanhf(a1a + a1b + c_bc);
            float kv2 = tanhf(a2a + a2b + c_bc);
            // ---- fused RK3 (Kutta) epilogue ----
            float u1, u2;
            if (i == 0) {
                k11 = kv1;  k12 = kv2;
                u1 = ry1 + 0.5f * hstep * kv1;
                u2 = ry2 + 0.5f * hstep * kv2;
            } else if (i == 1) {
                // u = y + h(-k1 + 2 k2); stash (k1 + 4 k2) in k1 regs
                u1 = ry1 + hstep * (2.f * kv1 - k11);
                u2 = ry2 + hstep * (2.f * kv2 - k12);
                k11 += 4.f * kv1;
                k12 += 4.f * kv2;
            } else {
                u1 = ry1 + (hstep * (1.f / 6.f)) * (k11 + kv1);
                u2 = ry2 + (hstep * (1.f / 6.f)) * (k12 + kv2);
                ry1 = u1; ry2 = u2;
            }
            // ---- push into every CTA's next A buffer ----
            const unsigned dstOff = ((s & 1) ? SA0_OFF : SA1_OFF) * 4u;
            const unsigned o1 = dstOff + jOff1;
            const unsigned o2 = dstOff + jOff2;
            #pragma unroll
            for (int p = 0; p < CLSZ; p++) {
                const unsigned mb = rmbar[p] + (unsigned)((s & 1) << 3);
                st_async(rbase[p] + o1, u1, mb);
                st_async(rbase[p] + o2, u2, mb);
            }
            s++;
        }

        // ---- GRU stage ----
        {
            const bool last = (t == T_ - 1);
            const unsigned mb_cur = mbase + (unsigned)((s & 1) << 3);
            if (tid == 0 && !last) expect_tx(mb_cur, TX_BYTES);
            mwait(mbase + (unsigned)(((s - 1) & 1) << 3),
                  (unsigned)(((s - 1) >> 1) & 1));
            const float* Ab = sm + ((s & 1) ? SA1_OFF : SA0_OFF);
            const float* pa1 = Ab + r1 * PAD;
            const float* pa2 = Ab + r2 * PAD;

            float ar1 = 0.f, az1 = 0.f, an1 = 0.f;
            float ar2 = 0.f, az2 = 0.f, an2 = 0.f;
            #pragma unroll 8
            for (int k = 0; k < H_; k += 4) {
                float4 u1 = *(const float4*)(pa1 + k);   // broadcast
                float4 u2 = *(const float4*)(pa2 + k);   // broadcast
                float4 br = *(const float4*)(pbr + k);   // unique per lane
                float4 bz = *(const float4*)(pbz + k);
                float4 bn = *(const float4*)(pbn + k);
                ar1 += u1.x*br.x + u1.y*br.y + u1.z*br.z + u1.w*br.w;
                az1 += u1.x*bz.x + u1.y*bz.y + u1.z*bz.z + u1.w*bz.w;
                an1 += u1.x*bn.x + u1.y*bn.y + u1.z*bn.z + u1.w*bn.w;
                ar2 += u2.x*br.x + u2.y*br.y + u2.z*br.z + u2.w*br.w;
                az2 += u2.x*bz.x + u2.y*bz.y + u2.z*bz.z + u2.w*bz.w;
                an2 += u2.x*bn.x + u2.y*bn.y + u2.z*bn.z + u2.w*bn.w;
            }
            {
                float x1 = __ldg(&batch[(b1r * T_ + t) * 2 + 1]);   // warp-uniform
                float m1 = __ldg(&mask[b1r * T_ + t]);
                float r_ = sigm(x1 * c_wir + c_bir + ar1 + c_bhr);
                float z_ = sigm(x1 * c_wiz + c_biz + az1 + c_bhz);
                float n_ = tanhf(x1 * c_win + c_bin + r_ * (an1 + c_bhn));
                float ht = (1.f - z_) * n_ + z_ * ry1;
                ry1 = m1 * ht + (1.f - m1) * ry1;
            }
            {
                float x2 = __ldg(&batch[(b2r * T_ + t) * 2 + 1]);
                float m2 = __ldg(&mask[b2r * T_ + t]);
                float r_ = sigm(x2 * c_wir + c_bir + ar2 + c_bhr);
                float z_ = sigm(x2 * c_wiz + c_biz + az2 + c_bhz);
                float n_ = tanhf(x2 * c_win + c_bin + r_ * (an2 + c_bhn));
                float ht = (1.f - z_) * n_ + z_ * ry2;
                ry2 = m2 * ht + (1.f - m2) * ry2;
            }
            if (!last) {
                const unsigned dstOff = ((s & 1) ? SA0_OFF : SA1_OFF) * 4u;
                const unsigned o1 = dstOff + jOff1;
                const unsigned o2 = dstOff + jOff2;
                #pragma unroll
                for (int p = 0; p < CLSZ; p++) {
                    const unsigned mb = rmbar[p] + (unsigned)((s & 1) << 3);
                    st_async(rbase[p] + o1, ry1, mb);
                    st_async(rbase[p] + o2, ry2, mb);
                }
            } else {
                out[b1r * H_ + j] = ry1;
                out[b2r * H_ + j] = ry2;
            }
            s++;
        }
    }
}

extern "C" void kernel_launch(void* const* d_in, const int* in_sizes, int n_in,
                              void* d_out, int out_size) {
    const float* batch = (const float*)d_in[0];
    const float* mask  = (const float*)d_in[1];
    const float* W1    = (const float*)d_in[2];
    const float* b1    = (const float*)d_in[3];
    const float* W2    = (const float*)d_in[4];
    const float* b2    = (const float*)d_in[5];
    const float* W_ih  = (const float*)d_in[6];
    const float* b_ih  = (const float*)d_in[7];
    const float* W_hh  = (const float*)d_in[8];
    const float* b_hh  = (const float*)d_in[9];
    float* out = (float*)d_out;

    cudaFuncSetAttribute(ode_rnn_kernel,
                         cudaFuncAttributeMaxDynamicSharedMemorySize,
                         SMEM_FLOATS * sizeof(float));

    ode_rnn_kernel<<<NCTA, NTHR, SMEM_FLOATS * sizeof(float)>>>(
        batch, mask, W1, b1, W2, b2, W_ih, b_ih, W_hh, b_hh, out);
}

// round 9
// speedup vs baseline: 1.5139x; 1.0021x over previous
#include <cuda_runtime.h>
#include <math.h>

#define B_   256
#define T_   64
#define H_   256
#define D_   512
#define NCTA 128
#define NTHR 256
#define CLSZ 8

#define PAD  260                        // smem row stride for weight tiles
// float offsets in dynamic smem:
#define SA0_OFF  0                      // A buffer phase 0: 8 blocks x 512 fl
#define SA1_OFF  4096                   // A buffer phase 1
#define STG_OFF  8192                   // staging: 2 x 512 fl
#define SWC_OFF  9216                   // Wc tile [32][PAD]
#define SWH_OFF  (SWC_OFF + 32 * PAD)   // W_hh gate tiles [3][32][PAD] (+scratch)
#define SMEM_FLOATS (SWH_OFF + 3 * 32 * PAD)   // 42496 fl = 169984 B

#define W2T_STRIDE 36                   // multiple of 4: float4-aligned scratch rows
#define TX_BYTES   (16 * H_ * 4)        // inbound bytes per stage = 16384
#define BLK_BYTES  2048                 // one 16x32 fp32 block

__device__ __forceinline__ unsigned s2u(const void* p) {
    unsigned a;
    asm("{ .reg .u64 t; cvta.to.shared.u64 t, %1; cvt.u32.u64 %0, t; }"
        : "=r"(a) : "l"(p));
    return a;
}

__device__ __forceinline__ void mwait(unsigned mbar, unsigned parity) {
    asm volatile(
        "{\n\t"
        ".reg .pred P;\n\t"
        "MW_LOOP_%=:\n\t"
        "mbarrier.try_wait.parity.shared.b64 P, [%0], %1;\n\t"
        "@!P bra MW_LOOP_%=;\n\t"
        "}"
        :: "r"(mbar), "r"(parity) : "memory");
}

__device__ __forceinline__ void expect_tx(unsigned mbar, unsigned bytes) {
    asm volatile("mbarrier.arrive.expect_tx.shared.b64 _, [%0], %1;"
                 :: "r"(mbar), "r"(bytes) : "memory");
}

// DSMEM bulk copy: local smem -> (possibly remote) cluster CTA smem,
// completion tx on the destination CTA's mbarrier.
__device__ __forceinline__ void bulk_dsmem(unsigned dst, unsigned src,
                                           unsigned bytes, unsigned dmbar) {
    asm volatile(
        "cp.async.bulk.shared::cluster.shared::cta.mbarrier::complete_tx::bytes "
        "[%0], [%1], %2, [%3];"
        :: "r"(dst), "r"(src), "r"(bytes), "r"(dmbar) : "memory");
}

__device__ __forceinline__ float sigm(float x) { return 1.f / (1.f + expf(-x)); }

// ---------------- persistent-group kernel ------------------------------------
__global__ void __launch_bounds__(NTHR, 1) __cluster_dims__(CLSZ, 1, 1)
ode_rnn_kernel(const float* __restrict__ batch, const float* __restrict__ mask,
               const float* __restrict__ W1,   const float* __restrict__ b1,
               const float* __restrict__ W2,   const float* __restrict__ b2,
               const float* __restrict__ W_ih, const float* __restrict__ b_ih,
               const float* __restrict__ W_hh, const float* __restrict__ b_hh,
               float* __restrict__ out)
{
    extern __shared__ float sm[];
    float* sWc  = sm + SWC_OFF;   // [32][PAD]  this CTA's Wc rows n0..n0+31
    float* sWh  = sm + SWH_OFF;   // [3][32][PAD] persistent W_hh gate tiles
    float* sW2T = sm + SWH_OFF;   // setup scratch: W2 tile transposed [512][36]

    __shared__ __align__(16) unsigned long long s_mbar[2];

    const int tid = threadIdx.x;
    const int mt  = blockIdx.x >> 3;       // cluster id = batch-row tile
    const int nt  = blockIdx.x & 7;        // rank in cluster = feature-col tile
    const int m0  = mt << 4;               // 16 batch rows
    const int n0  = nt << 5;               // 32 feature cols
    const int w   = tid >> 5;              // warp 0..7
    const int l   = tid & 31;
    // crossbar-optimal mapping: warp owns 4 cols, lane quad owns row pair
    const int jc  = (w << 2) + (l & 3);    // owned col within tile 0..31
    const int r1  = l >> 2;                // owned rows r1, r1+8  (r1 in 0..7)
    const int r2  = r1 + 8;
    const int s1  = r1;                    // swizzle key (= r1&7 = r2&7)

    const int b1r = m0 + r1;
    const int b2r = m0 + r2;
    const int j   = n0 + jc;

    const unsigned smbase = s2u(sm);
    const unsigned mbase  = s2u(s_mbar);

    // ================= setup (group-local) =================
    // zero A buffer phase 0 (u0 = 0, all 8 blocks)
    for (int idx = tid; idx < 4096; idx += NTHR) sm[SA0_OFF + idx] = 0.f;

    // stage W2 rows n0..n0+31 into smem, transposed: sW2T[d][j']
    for (int idx = tid; idx < 32 * (D_ / 4); idx += NTHR) {
        int jj = idx >> 7;                 // 0..31
        int d4 = (idx & 127) << 2;         // 0,4,...,508
        float4 v = __ldg((const float4*)&W2[(size_t)(n0 + jj) * D_ + d4]);
        sW2T[(d4 + 0) * W2T_STRIDE + jj] = v.x;
        sW2T[(d4 + 1) * W2T_STRIDE + jj] = v.y;
        sW2T[(d4 + 2) * W2T_STRIDE + jj] = v.z;
        sW2T[(d4 + 3) * W2T_STRIDE + jj] = v.w;
    }
    __syncthreads();

    // Wc tile: sWc[j'][h] = sum_d W2[n0+j'][d] * W1[d][h], h = tid
    #pragma unroll
    for (int p = 0; p < 2; p++) {
        float acc[16];
        #pragma unroll
        for (int jj = 0; jj < 16; jj++) acc[jj] = 0.f;
        for (int d = 0; d < D_; d++) {
            float w1v = __ldg(&W1[(size_t)d * H_ + tid]);   // coalesced
            const float* w2d = &sW2T[d * W2T_STRIDE + p * 16];
            #pragma unroll
            for (int jj = 0; jj < 16; jj += 4) {
                float4 wv = *(const float4*)(w2d + jj);     // aligned broadcast
                acc[jj + 0] += wv.x * w1v;
                acc[jj + 1] += wv.y * w1v;
                acc[jj + 2] += wv.z * w1v;
                acc[jj + 3] += wv.w * w1v;
            }
        }
        #pragma unroll
        for (int jj = 0; jj < 16; jj++)
            sWc[(p * 16 + jj) * PAD + tid] = acc[jj];
    }
    // bc for this thread's fixed column j
    float c_bc;
    {
        float s = 0.f;
        for (int d = 0; d < D_; d++)
            s += sW2T[d * W2T_STRIDE + jc] * __ldg(&b1[d]);
        c_bc = s + __ldg(&b2[j]);
    }
    __syncthreads();   // sW2T reads done before overwrite

    // persistent W_hh gate tiles (overwrites scratch)
    for (int idx = tid; idx < 3 * 32 * 64; idx += NTHR) {
        int g = idx >> 11, r = (idx >> 6) & 31, q = (idx & 63) << 2;
        float4 v = __ldg((const float4*)&W_hh[(size_t)(g * H_ + n0 + r) * H_ + q]);
        *(float4*)&sWh[(g * 32 + r) * PAD + q] = v;
    }

    // per-thread constants
    const float c_bhr = __ldg(&b_hh[j]);
    const float c_bhz = __ldg(&b_hh[j + 256]);
    const float c_bhn = __ldg(&b_hh[j + 512]);
    const float c_wir = __ldg(&W_ih[j]);
    const float c_wiz = __ldg(&W_ih[j + 256]);
    const float c_win = __ldg(&W_ih[j + 512]);
    const float c_bir = __ldg(&b_ih[j]);
    const float c_biz = __ldg(&b_ih[j + 256]);
    const float c_bin = __ldg(&b_ih[j + 512]);

    // mbarriers: 1 expected arrival per phase (tid0's expect_tx)
    if (tid == 0) {
        asm volatile("mbarrier.init.shared.b64 [%0], 1;" :: "r"(mbase)     : "memory");
        asm volatile("mbarrier.init.shared.b64 [%0], 1;" :: "r"(mbase + 8) : "memory");
    }
    __syncthreads();
    // one-time cluster sync: mbarriers + smem init visible before any bulk copy
    asm volatile("barrier.cluster.arrive.aligned;" ::: "memory");
    asm volatile("barrier.cluster.wait.aligned;"   ::: "memory");

    // remote bases for all 8 cluster ranks
    unsigned rbase[CLSZ], rmbar[CLSZ];
    #pragma unroll
    for (int p = 0; p < CLSZ; p++) {
        asm("mapa.shared::cluster.u32 %0, %1, %2;" : "=r"(rbase[p]) : "r"(smbase), "r"(p));
        asm("mapa.shared::cluster.u32 %0, %1, %2;" : "=r"(rmbar[p]) : "r"(mbase),  "r"(p));
    }

    // staging write offsets (swizzled: chunk c -> c ^ (row&7))
    const int soff1 = r1 * 32 + ((((jc >> 2) ^ s1) << 2) | (jc & 3));
    const int soff2 = soff1 + 256;       // row + 8: same swizzle key

    const float* pbc = sWc + jc * PAD;
    const float* pbr = sWh + (0 * 32 + jc) * PAD;
    const float* pbz = sWh + (1 * 32 + jc) * PAD;
    const float* pbn = sWh + (2 * 32 + jc) * PAD;

    float ry1 = 0.f, ry2 = 0.f;     // ODE base state (registers)
    float k11 = 0.f, k12 = 0.f;     // RK3 k1 keep

    // ================= time loop =================
    int   s = 0;                    // global stage index (4 per timestep)
    float tprev = 0.f;
    for (int t = 0; t < T_; t++) {
        const float tcur  = __ldg(&batch[2 * t]);
        const float hstep = tcur - tprev;      // single RK3 step per interval
        tprev = tcur;

        #pragma unroll
        for (int i = 0; i < 3; i++) {
            // ---- stage prologue ----
            if (tid == 0) expect_tx(mbase + (unsigned)((s & 1) << 3), TX_BYTES);
            if (s > 0) mwait(mbase + (unsigned)(((s - 1) & 1) << 3),
                             (unsigned)(((s - 1) >> 1) & 1));
            const float* Ab = sm + ((s & 1) ? SA1_OFF : SA0_OFF);
            // ---- GEMM: 2 dots of K=256 over 8 swizzled blocks ----
            float a1a = 0.f, a1b = 0.f, a2a = 0.f, a2b = 0.f;
            #pragma unroll
            for (int p = 0; p < 8; p++) {
                const float* bp1 = Ab + p * 512 + r1 * 32;
                const float* bp2 = bp1 + 256;
                const float* bb  = pbc + p * 32;
                #pragma unroll
                for (int c = 0; c < 8; c++) {
                    const int sc = (c ^ s1) << 2;
                    float4 b4 = *(const float4*)(bb + (c << 2));
                    float4 u1 = *(const float4*)(bp1 + sc);
                    float4 u2 = *(const float4*)(bp2 + sc);
                    if (c & 1) {
                        a1b += u1.x*b4.x; a1b += u1.y*b4.y;
                        a1b += u1.z*b4.z; a1b += u1.w*b4.w;
                        a2b += u2.x*b4.x; a2b += u2.y*b4.y;
                        a2b += u2.z*b4.z; a2b += u2.w*b4.w;
                    } else {
                        a1a += u1.x*b4.x; a1a += u1.y*b4.y;
                        a1a += u1.z*b4.z; a1a += u1.w*b4.w;
                        a2a += u2.x*b4.x; a2a += u2.y*b4.y;
                        a2a += u2.z*b4.z; a2a += u2.w*b4.w;
                    }
                }
            }
            float kv1 = tanhf(a1a + a1b + c_bc);
            float kv2 = tanhf(a2a + a2b + c_bc);
            // ---- fused RK3 (Kutta) epilogue ----
            float u1, u2;
            if (i == 0) {
                k11 = kv1;  k12 = kv2;
                u1 = ry1 + 0.5f * hstep * kv1;
                u2 = ry2 + 0.5f * hstep * kv2;
            } else if (i == 1) {
                u1 = ry1 + hstep * (2.f * kv1 - k11);
                u2 = ry2 + hstep * (2.f * kv2 - k12);
                k11 += 4.f * kv1;
                k12 += 4.f * kv2;
            } else {
                u1 = ry1 + (hstep * (1.f / 6.f)) * (k11 + kv1);
                u2 = ry2 + (hstep * (1.f / 6.f)) * (k12 + kv2);
                ry1 = u1; ry2 = u2;
            }
            // ---- stage to local swizzled block, bulk-copy to all ranks ----
            float* stg = sm + STG_OFF + ((s & 1) << 9);
            stg[soff1] = u1;
            stg[soff2] = u2;
            __syncthreads();
            asm volatile("fence.proxy.async.shared::cta;" ::: "memory");
            if (tid < CLSZ) {
                const unsigned dstOff = (unsigned)(((s & 1) ? SA0_OFF : SA1_OFF) * 4
                                                   + nt * BLK_BYTES);
                const unsigned src = smbase + (unsigned)((STG_OFF + ((s & 1) << 9)) * 4);
                bulk_dsmem(rbase[tid] + dstOff, src, BLK_BYTES,
                           rmbar[tid] + (unsigned)((s & 1) << 3));
            }
            s++;
        }

        // ---- GRU stage ----
        {
            const bool last = (t == T_ - 1);
            if (tid == 0 && !last) expect_tx(mbase + (unsigned)((s & 1) << 3), TX_BYTES);
            mwait(mbase + (unsigned)(((s - 1) & 1) << 3),
                  (unsigned)(((s - 1) >> 1) & 1));
            const float* Ab = sm + ((s & 1) ? SA1_OFF : SA0_OFF);

            float ar1 = 0.f, az1 = 0.f, an1 = 0.f;
            float ar2 = 0.f, az2 = 0.f, an2 = 0.f;
            #pragma unroll
            for (int p = 0; p < 8; p++) {
                const float* bp1 = Ab + p * 512 + r1 * 32;
                const float* bp2 = bp1 + 256;
                const int kb = p * 32;
                #pragma unroll
                for (int c = 0; c < 8; c++) {
                    const int sc = (c ^ s1) << 2;
                    const int k  = kb + (c << 2);
                    float4 u1 = *(const float4*)(bp1 + sc);
                    float4 u2 = *(const float4*)(bp2 + sc);
                    float4 br = *(const float4*)(pbr + k);
                    float4 bz = *(const float4*)(pbz + k);
                    float4 bn = *(const float4*)(pbn + k);
                    ar1 += u1.x*br.x + u1.y*br.y + u1.z*br.z + u1.w*br.w;
                    az1 += u1.x*bz.x + u1.y*bz.y + u1.z*bz.z + u1.w*bz.w;
                    an1 += u1.x*bn.x + u1.y*bn.y + u1.z*bn.z + u1.w*bn.w;
                    ar2 += u2.x*br.x + u2.y*br.y + u2.z*br.z + u2.w*br.w;
                    az2 += u2.x*bz.x + u2.y*bz.y + u2.z*bz.z + u2.w*bz.w;
                    an2 += u2.x*bn.x + u2.y*bn.y + u2.z*bn.z + u2.w*bn.w;
                }
            }
            {
                float x1 = __ldg(&batch[(b1r * T_ + t) * 2 + 1]);
                float m1 = __ldg(&mask[b1r * T_ + t]);
                float r_ = sigm(x1 * c_wir + c_bir + ar1 + c_bhr);
                float z_ = sigm(x1 * c_wiz + c_biz + az1 + c_bhz);
                float n_ = tanhf(x1 * c_win + c_bin + r_ * (an1 + c_bhn));
                float ht = (1.f - z_) * n_ + z_ * ry1;
                ry1 = m1 * ht + (1.f - m1) * ry1;
            }
            {
                float x2 = __ldg(&batch[(b2r * T_ + t) * 2 + 1]);
                float m2 = __ldg(&mask[b2r * T_ + t]);
                float r_ = sigm(x2 * c_wir + c_bir + ar2 + c_bhr);
                float z_ = sigm(x2 * c_wiz + c_biz + az2 + c_bhz);
                float n_ = tanhf(x2 * c_win + c_bin + r_ * (an2 + c_bhn));
                float ht = (1.f - z_) * n_ + z_ * ry2;
                ry2 = m2 * ht + (1.f - m2) * ry2;
            }
            if (!last) {
                float* stg = sm + STG_OFF + ((s & 1) << 9);
                stg[soff1] = ry1;
                stg[soff2] = ry2;
                __syncthreads();
                asm volatile("fence.proxy.async.shared::cta;" ::: "memory");
                if (tid < CLSZ) {
                    const unsigned dstOff = (unsigned)(((s & 1) ? SA0_OFF : SA1_OFF) * 4
                                                       + nt * BLK_BYTES);
                    const unsigned src = smbase + (unsigned)((STG_OFF + ((s & 1) << 9)) * 4);
                    bulk_dsmem(rbase[tid] + dstOff, src, BLK_BYTES,
                               rmbar[tid] + (unsigned)((s & 1) << 3));
                }
            } else {
                out[b1r * H_ + j] = ry1;
                out[b2r * H_ + j] = ry2;
            }
            s++;
        }
    }
}

extern "C" void kernel_launch(void* const* d_in, const int* in_sizes, int n_in,
                              void* d_out, int out_size) {
    const float* batch = (const float*)d_in[0];
    const float* mask  = (const float*)d_in[1];
    const float* W1    = (const float*)d_in[2];
    const float* b1    = (const float*)d_in[3];
    const float* W2    = (const float*)d_in[4];
    const float* b2    = (const float*)d_in[5];
    const float* W_ih  = (const float*)d_in[6];
    const float* b_ih  = (const float*)d_in[7];
    const float* W_hh  = (const float*)d_in[8];
    const float* b_hh  = (const float*)d_in[9];
    float* out = (float*)d_out;

    cudaFuncSetAttribute(ode_rnn_kernel,
                         cudaFuncAttributeMaxDynamicSharedMemorySize,
                         SMEM_FLOATS * sizeof(float));

    ode_rnn_kernel<<<NCTA, NTHR, SMEM_FLOATS * sizeof(float)>>>(
        batch, mask, W1, b1, W2, b2, W_ih, b_ih, W_hh, b_hh, out);
}

// round 11
// speedup vs baseline: 1.6279x; 1.0753x over previous
#include <cuda_runtime.h>
#include <math.h>

#define B_   256
#define T_   64
#define H_   256
#define D_   512
#define NCTA 128
#define NTHR 256
#define CLSZ 8

#define PAD  260                        // smem row stride for weight tiles
// float offsets in dynamic smem:
#define SA0_OFF  0                      // A buffer phase 0: 8 chunks x 512 fl
#define SA1_OFF  4096                   // A buffer phase 1
#define SWC_OFF  8192                   // Wc tile [32][PAD]
#define SWH_OFF  (SWC_OFF + 32 * PAD)   // W_hh gate tiles [3][32][PAD] (+scratch)
#define SMEM_FLOATS (SWH_OFF + 3 * 32 * PAD)   // 41472 fl = 165888 B

#define W2T_STRIDE 36                   // multiple of 4: float4-aligned scratch rows
#define CHUNK_BYTES 2048                // one 16x32 fp32 chunk

__device__ __forceinline__ unsigned s2u(const void* p) {
    unsigned a;
    asm("{ .reg .u64 t; cvta.to.shared.u64 t, %1; cvt.u32.u64 %0, t; }"
        : "=r"(a) : "l"(p));
    return a;
}

__device__ __forceinline__ void mwait(unsigned mbar, unsigned parity) {
    asm volatile(
        "{\n\t"
        ".reg .pred P;\n\t"
        "MW_LOOP_%=:\n\t"
        "mbarrier.try_wait.parity.shared.b64 P, [%0], %1;\n\t"
        "@!P bra MW_LOOP_%=;\n\t"
        "}"
        :: "r"(mbar), "r"(parity) : "memory");
}

// arrive(1) + expect_tx(bytes) in one op: the arming arrive for this phase
__device__ __forceinline__ void arm_tx(unsigned mbar, unsigned bytes) {
    asm volatile("mbarrier.arrive.expect_tx.shared.b64 _, [%0], %1;"
                 :: "r"(mbar), "r"(bytes) : "memory");
}

// DSMEM bulk copy: local smem -> remote cluster CTA smem, tx on dest mbarrier
__device__ __forceinline__ void bulk_dsmem(unsigned dst, unsigned src,
                                           unsigned bytes, unsigned dmbar) {
    asm volatile(
        "cp.async.bulk.shared::cluster.shared::cta.mbarrier::complete_tx::bytes "
        "[%0], [%1], %2, [%3];"
        :: "r"(dst), "r"(src), "r"(bytes), "r"(dmbar) : "memory");
}

__device__ __forceinline__ float sigm(float x) { return 1.f / (1.f + expf(-x)); }

// ---------------- persistent-group kernel ------------------------------------
__global__ void __launch_bounds__(NTHR, 1) __cluster_dims__(CLSZ, 1, 1)
ode_rnn_kernel(const float* __restrict__ batch, const float* __restrict__ mask,
               const float* __restrict__ W1,   const float* __restrict__ b1,
               const float* __restrict__ W2,   const float* __restrict__ b2,
               const float* __restrict__ W_ih, const float* __restrict__ b_ih,
               const float* __restrict__ W_hh, const float* __restrict__ b_hh,
               float* __restrict__ out)
{
    extern __shared__ float sm[];
    float* sWc  = sm + SWC_OFF;   // [32][PAD]  this CTA's Wc rows n0..n0+31
    float* sWh  = sm + SWH_OFF;   // [3][32][PAD] persistent W_hh gate tiles
    float* sW2T = sm + SWH_OFF;   // setup scratch: W2 tile transposed [512][36]

    __shared__ __align__(16) unsigned long long s_mbar[16];   // [phase][chunk]

    const int tid = threadIdx.x;
    const int mt  = blockIdx.x >> 3;       // cluster id = batch-row tile
    const int nt  = blockIdx.x & 7;        // rank in cluster = feature-col tile
    const int m0  = mt << 4;               // 16 batch rows
    const int n0  = nt << 5;               // 32 feature cols
    const int w   = tid >> 5;              // warp 0..7 -> col group
    const int l   = tid & 31;
    const int jc  = (w << 2) + (l & 3);    // owned col within tile 0..31
    const int r1  = l >> 2;                // owned rows r1, r1+8  (0..7)
    const int r2  = r1 + 8;

    const int b1r = m0 + r1;
    const int b2r = m0 + r2;
    const int j   = n0 + jc;

    const unsigned smbase = s2u(sm);
    const unsigned mbase  = s2u(s_mbar);

    // ================= setup (group-local) =================
    for (int idx = tid; idx < 4096; idx += NTHR) sm[SA0_OFF + idx] = 0.f;  // u0 = 0

    // stage W2 rows n0..n0+31 into smem, transposed: sW2T[d][j']
    for (int idx = tid; idx < 32 * (D_ / 4); idx += NTHR) {
        int jj = idx >> 7;
        int d4 = (idx & 127) << 2;
        float4 v = __ldg((const float4*)&W2[(size_t)(n0 + jj) * D_ + d4]);
        sW2T[(d4 + 0) * W2T_STRIDE + jj] = v.x;
        sW2T[(d4 + 1) * W2T_STRIDE + jj] = v.y;
        sW2T[(d4 + 2) * W2T_STRIDE + jj] = v.z;
        sW2T[(d4 + 3) * W2T_STRIDE + jj] = v.w;
    }
    __syncthreads();

    // Wc tile: sWc[j'][h] = sum_d W2[n0+j'][d] * W1[d][h], h = tid
    #pragma unroll
    for (int p = 0; p < 2; p++) {
        float acc[16];
        #pragma unroll
        for (int jj = 0; jj < 16; jj++) acc[jj] = 0.f;
        for (int d = 0; d < D_; d++) {
            float w1v = __ldg(&W1[(size_t)d * H_ + tid]);
            const float* w2d = &sW2T[d * W2T_STRIDE + p * 16];
            #pragma unroll
            for (int jj = 0; jj < 16; jj += 4) {
                float4 wv = *(const float4*)(w2d + jj);
                acc[jj + 0] += wv.x * w1v;
                acc[jj + 1] += wv.y * w1v;
                acc[jj + 2] += wv.z * w1v;
                acc[jj + 3] += wv.w * w1v;
            }
        }
        #pragma unroll
        for (int jj = 0; jj < 16; jj++)
            sWc[(p * 16 + jj) * PAD + tid] = acc[jj];
    }
    float c_bc;
    {
        float s = 0.f;
        for (int d = 0; d < D_; d++)
            s += sW2T[d * W2T_STRIDE + jc] * __ldg(&b1[d]);
        c_bc = s + __ldg(&b2[j]);
    }
    __syncthreads();   // sW2T reads done before overwrite

    for (int idx = tid; idx < 3 * 32 * 64; idx += NTHR) {
        int g = idx >> 11, r = (idx >> 6) & 31, q = (idx & 63) << 2;
        float4 v = __ldg((const float4*)&W_hh[(size_t)(g * H_ + n0 + r) * H_ + q]);
        *(float4*)&sWh[(g * 32 + r) * PAD + q] = v;
    }

    const float c_bhr = __ldg(&b_hh[j]);
    const float c_bhz = __ldg(&b_hh[j + 256]);
    const float c_bhn = __ldg(&b_hh[j + 512]);
    const float c_wir = __ldg(&W_ih[j]);
    const float c_wiz = __ldg(&W_ih[j + 256]);
    const float c_win = __ldg(&W_ih[j + 512]);
    const float c_bir = __ldg(&b_ih[j]);
    const float c_biz = __ldg(&b_ih[j + 256]);
    const float c_bin = __ldg(&b_ih[j + 512]);

    if (tid < 16) {
        asm volatile("mbarrier.init.shared.b64 [%0], 1;"
                     :: "r"(mbase + tid * 8) : "memory");
    }
    __syncthreads();
    asm volatile("barrier.cluster.arrive.aligned;" ::: "memory");
    asm volatile("barrier.cluster.wait.aligned;"   ::: "memory");

    unsigned rbase[CLSZ], rmbar[CLSZ];
    #pragma unroll
    for (int p = 0; p < CLSZ; p++) {
        asm("mapa.shared::cluster.u32 %0, %1, %2;" : "=r"(rbase[p]) : "r"(smbase), "r"(p));
        asm("mapa.shared::cluster.u32 %0, %1, %2;" : "=r"(rmbar[p]) : "r"(mbase),  "r"(p));
    }

    // within-chunk swizzled offsets for this thread's two outputs
    const int soff1 = r1 * 32 + (((w ^ r1) << 2) | (l & 3));
    const int soff2 = soff1 + 256;

    const float* pbc = sWc + jc * PAD;
    const float* pbr = sWh + (0 * 32 + jc) * PAD;
    const float* pbz = sWh + (1 * 32 + jc) * PAD;
    const float* pbn = sWh + (2 * 32 + jc) * PAD;

    float ry1 = 0.f, ry2 = 0.f;     // ODE base state
    float k11 = 0.f, k12 = 0.f;     // RK3 k1 keep

    // ================= time loop =================
    int   s = 0;                    // global stage index (4 per timestep)
    float tprev = 0.f;
    for (int t = 0; t < T_; t++) {
        const float tcur  = __ldg(&batch[2 * t]);
        const float hstep = tcur - tprev;
        tprev = tcur;

        #pragma unroll
        for (int i = 0; i < 4; i++) {
            const bool gru  = (i == 3);
            const bool last = gru && (t == T_ - 1);
            // arm receive barriers for THIS stage's outgoing data (set s&1)
            if (!last && tid < 8 && tid != nt)
                arm_tx(mbase + (unsigned)(((s & 1) << 3) + tid) * 8u, CHUNK_BYTES);

            const float* Ab = sm + ((s & 1) ? SA1_OFF : SA0_OFF);
            const unsigned wset = (unsigned)(((s - 1) & 1) << 3);
            const unsigned wpar = (unsigned)(((s - 1) >> 1) & 1);

            float x1, x2, mk1, mk2;
            if (gru) {                          // prefetch GRU scalars early
                x1  = __ldg(&batch[(b1r * T_ + t) * 2 + 1]);
                x2  = __ldg(&batch[(b2r * T_ + t) * 2 + 1]);
                mk1 = __ldg(&mask[b1r * T_ + t]);
                mk2 = __ldg(&mask[b2r * T_ + t]);
            }

            float acc1 = 0.f, acc2 = 0.f;                    // ODE dots
            float ar1 = 0.f, az1 = 0.f, an1 = 0.f;           // GRU dots
            float ar2 = 0.f, az2 = 0.f, an2 = 0.f;

            for (int q = 0; q < 8; q++) {
                const int p = (nt + q) & 7;
                if (s > 0 && q > 0)
                    mwait(mbase + (wset + (unsigned)p) * 8u, wpar);
                const float* cb1 = Ab + p * 512 + r1 * 32;
                const float* cb2 = cb1 + 256;
                if (!gru) {
                    const float* bb = pbc + p * 32;
                    #pragma unroll
                    for (int c = 0; c < 8; c++) {
                        const int sc = (c ^ r1) << 2;
                        float4 b4 = *(const float4*)(bb + (c << 2));
                        float4 u1 = *(const float4*)(cb1 + sc);
                        float4 u2 = *(const float4*)(cb2 + sc);
                        acc1 += u1.x*b4.x; acc1 += u1.y*b4.y;
                        acc1 += u1.z*b4.z; acc1 += u1.w*b4.w;
                        acc2 += u2.x*b4.x; acc2 += u2.y*b4.y;
                        acc2 += u2.z*b4.z; acc2 += u2.w*b4.w;
                    }
                } else {
                    const int kb = p * 32;
                    #pragma unroll
                    for (int c = 0; c < 8; c++) {
                        const int sc = (c ^ r1) << 2;
                        const int k  = kb + (c << 2);
                        float4 u1 = *(const float4*)(cb1 + sc);
                        float4 u2 = *(const float4*)(cb2 + sc);
                        float4 br = *(const float4*)(pbr + k);
                        float4 bz = *(const float4*)(pbz + k);
                        float4 bn = *(const float4*)(pbn + k);
                        ar1 += u1.x*br.x + u1.y*br.y + u1.z*br.z + u1.w*br.w;
                        az1 += u1.x*bz.x + u1.y*bz.y + u1.z*bz.z + u1.w*bz.w;
                        an1 += u1.x*bn.x + u1.y*bn.y + u1.z*bn.z + u1.w*bn.w;
                        ar2 += u2.x*br.x + u2.y*br.y + u2.z*br.z + u2.w*br.w;
                        az2 += u2.x*bz.x + u2.y*bz.y + u2.z*bz.z + u2.w*bz.w;
                        an2 += u2.x*bn.x + u2.y*bn.y + u2.z*bn.z + u2.w*bn.w;
                    }
                }
            }

            // ---- epilogue ----
            float u1, u2;
            if (!gru) {
                float kv1 = tanhf(acc1 + c_bc);
                float kv2 = tanhf(acc2 + c_bc);
                if (i == 0) {
                    k11 = kv1;  k12 = kv2;
                    u1 = ry1 + 0.5f * hstep * kv1;
                    u2 = ry2 + 0.5f * hstep * kv2;
                } else if (i == 1) {
                    u1 = ry1 + hstep * (2.f * kv1 - k11);
                    u2 = ry2 + hstep * (2.f * kv2 - k12);
                    k11 += 4.f * kv1;
                    k12 += 4.f * kv2;
                } else {
                    u1 = ry1 + (hstep * (1.f / 6.f)) * (k11 + kv1);
                    u2 = ry2 + (hstep * (1.f / 6.f)) * (k12 + kv2);
                    ry1 = u1; ry2 = u2;
                }
            } else {
                {
                    float r_ = sigm(x1 * c_wir + c_bir + ar1 + c_bhr);
                    float z_ = sigm(x1 * c_wiz + c_biz + az1 + c_bhz);
                    float n_ = tanhf(x1 * c_win + c_bin + r_ * (an1 + c_bhn));
                    float ht = (1.f - z_) * n_ + z_ * ry1;
                    ry1 = mk1 * ht + (1.f - mk1) * ry1;
                }
                {
                    float r_ = sigm(x2 * c_wir + c_bir + ar2 + c_bhr);
                    float z_ = sigm(x2 * c_wiz + c_biz + az2 + c_bhz);
                    float n_ = tanhf(x2 * c_win + c_bin + r_ * (an2 + c_bhn));
                    float ht = (1.f - z_) * n_ + z_ * ry2;
                    ry2 = mk2 * ht + (1.f - mk2) * ry2;
                }
                u1 = ry1; u2 = ry2;
            }

            if (!last) {
                // own chunk straight into next A buffer (also bulk source)
                const int nextpb = (s & 1) ? SA0_OFF : SA1_OFF;
                float* Anext = sm + nextpb + nt * 512;
                Anext[soff1] = u1;
                Anext[soff2] = u2;
                __syncthreads();                 // all STS done before engine reads
                if (tid < 8 && tid != nt) {
                    asm volatile("fence.proxy.async.shared::cta;" ::: "memory");
                    const unsigned off = (unsigned)(nextpb + nt * 512) * 4u;
                    bulk_dsmem(rbase[tid] + off, smbase + off, CHUNK_BYTES,
                               rmbar[tid] + (unsigned)(((s & 1) << 3) + nt) * 8u);
                }
            } else {
                out[b1r * H_ + j] = ry1;
                out[b2r * H_ + j] = ry2;
            }
            s++;
        }
    }
}

extern "C" void kernel_launch(void* const* d_in, const int* in_sizes, int n_in,
                              void* d_out, int out_size) {
    const float* batch = (const float*)d_in[0];
    const float* mask  = (const float*)d_in[1];
    const float* W1    = (const float*)d_in[2];
    const float* b1    = (const float*)d_in[3];
    const float* W2    = (const float*)d_in[4];
    const float* b2    = (const float*)d_in[5];
    const float* W_ih  = (const float*)d_in[6];
    const float* b_ih  = (const float*)d_in[7];
    const float* W_hh  = (const float*)d_in[8];
    const float* b_hh  = (const float*)d_in[9];
    float* out = (float*)d_out;

    cudaFuncSetAttribute(ode_rnn_kernel,
                         cudaFuncAttributeMaxDynamicSharedMemorySize,
                         SMEM_FLOATS * sizeof(float));

    ode_rnn_kernel<<<NCTA, NTHR, SMEM_FLOATS * sizeof(float)>>>(
        batch, mask, W1, b1, W2, b2, W_ih, b_ih, W_hh, b_hh, out);
}